// round 10
// baseline (speedup 1.0000x reference)
#include <cuda_runtime.h>
#include <cuda_bf16.h>
#include <math.h>
#include <stdint.h>

#define NTOT   8192
#define BHALF  4096
#define DDIM   256
#define MT     128                  // rows per tile-block
#define CT     128                  // cols per tile
#define NRB    (NTOT / MT)          // 64 row-blocks
#define AS8    272                  // smem row stride bytes (256 data + 16 pad)
#define TILE8  (MT * AS8)           // 34816 B: full A tile
#define HB     (64 * AS8)           // 17408 B: half B tile (64 rows)
#define NCHUNK 9                    // chunks per strip-pair -> grid 288 = 2 CTAs/SM
#define NCTA   (32 * NCHUNK)        // 288
#define THREADS 512

// Scratch: int8-quantized normalized vectors (q = round(127*zhat)),
// per-row sum-exp, per-row positive logit, completion ticket
__device__ int8_t g_q[NTOT * DDIM];
__device__ float g_rowsum[NTOT];
__device__ float g_pos[NTOT];
__device__ unsigned g_ticket;

// ---------------------------------------------------------------------------
__device__ __forceinline__ uint32_t smem_u32(const void* p) {
    uint32_t a;
    asm("{ .reg .u64 t; cvta.to.shared.u64 t, %1; cvt.u32.u64 %0, t; }"
        : "=r"(a) : "l"(p));
    return a;
}
__device__ __forceinline__ float ex2f(float x) {     // 2^x on MUFU pipe
    float r;
    asm("ex2.approx.f32 %0, %1;" : "=f"(r) : "f"(x));
    return r;
}
#define CP_ASYNC16(dst, src) \
    asm volatile("cp.async.cg.shared.global [%0], [%1], 16;" :: "r"(dst), "l"(src))
#define CP_COMMIT() asm volatile("cp.async.commit_group;" ::: "memory")
#define CP_WAIT(n)  asm volatile("cp.async.wait_group %0;" :: "n"(n) : "memory")
// warp-group barrier: 256 threads, id 1+wg (0 reserved for __syncthreads)
#define BARWG(wg) \
    asm volatile("bar.sync %0, %1;" :: "r"(1 + (wg)), "r"(256) : "memory")

#define LDSM_X4(r0, r1, r2, r3, a)                                        \
    asm volatile("ldmatrix.sync.aligned.m8n8.x4.shared.b16 {%0,%1,%2,%3}, [%4];" \
        : "=r"(r0), "=r"(r1), "=r"(r2), "=r"(r3) : "r"(a))

#define MMAS8(d, a0, a1, a2, a3, b0, b1)                                  \
    asm volatile("mma.sync.aligned.m16n8k32.row.col.s32.s8.s8.s32 "       \
        "{%0,%1,%2,%3}, {%4,%5,%6,%7}, {%8,%9}, {%0,%1,%2,%3};"           \
        : "+r"((d)[0]), "+r"((d)[1]), "+r"((d)[2]), "+r"((d)[3])          \
        : "r"(a0), "r"(a1), "r"(a2), "r"(a3), "r"(b0), "r"(b1))

// ---------------------------------------------------------------------------
// Prep: each warp handles 4 rows, 8 LDG.128 in flight, 4 parallel reductions.
// Also zeroes g_rowsum / g_ticket.
// ---------------------------------------------------------------------------
__device__ __forceinline__ const float* row_ptr(int row,
        const float* zi, const float* zj) {
    return (row < BHALF) ? (zi + (size_t)row * DDIM)
                         : (zj + (size_t)(row - BHALF) * DDIM);
}
__device__ __forceinline__ void quant_store(int row, float sc,
        float4 v0, float4 v1, int lane) {
    int q0 = __float2int_rn(v0.x * sc), q1 = __float2int_rn(v0.y * sc);
    int q2 = __float2int_rn(v0.z * sc), q3 = __float2int_rn(v0.w * sc);
    int q4 = __float2int_rn(v1.x * sc), q5 = __float2int_rn(v1.y * sc);
    int q6 = __float2int_rn(v1.z * sc), q7 = __float2int_rn(v1.w * sc);
    uint2 pk;
    pk.x = (q0 & 0xff) | ((q1 & 0xff) << 8) | ((q2 & 0xff) << 16) | (q3 << 24);
    pk.y = (q4 & 0xff) | ((q5 & 0xff) << 8) | ((q6 & 0xff) << 16) | (q7 << 24);
    *(uint2*)(g_q + (size_t)row * DDIM + lane * 8) = pk;
}

__global__ void k_prep(const float* __restrict__ zi, const float* __restrict__ zj) {
    if (blockIdx.x < 32) g_rowsum[blockIdx.x * 256 + threadIdx.x] = 0.0f;
    if (blockIdx.x == 0 && threadIdx.x == 0) g_ticket = 0u;

    const int warp = threadIdx.x >> 5;
    const int lane = threadIdx.x & 31;
    const int r0 = blockIdx.x * 32 + warp * 4;

    float4 v[8];
    #pragma unroll
    for (int r = 0; r < 4; r++) {
        const float* s = row_ptr(r0 + r, zi, zj);
        v[2*r]   = ((const float4*)s)[lane * 2 + 0];
        v[2*r+1] = ((const float4*)s)[lane * 2 + 1];
    }
    float ss[4];
    #pragma unroll
    for (int r = 0; r < 4; r++) {
        float4 a = v[2*r], b = v[2*r+1];
        ss[r] = a.x*a.x + a.y*a.y + a.z*a.z + a.w*a.w
              + b.x*b.x + b.y*b.y + b.z*b.z + b.w*b.w;
    }
    #pragma unroll
    for (int o = 16; o; o >>= 1)
        #pragma unroll
        for (int r = 0; r < 4; r++)
            ss[r] += __shfl_xor_sync(0xffffffffu, ss[r], o);
    #pragma unroll
    for (int r = 0; r < 4; r++)
        quant_store(r0 + r, 127.0f * rsqrtf(ss[r]), v[2*r], v[2*r+1], lane);
}

// ---------------------------------------------------------------------------
// Loaders: full A tile (all 512 threads), or one 64-row B half (256 wg threads)
// ---------------------------------------------------------------------------
__device__ __forceinline__ void load_tile_async(uint32_t dst, int grow0) {
    const int tid = threadIdx.x;
    #pragma unroll
    for (int i = 0; i < 4; i++) {
        int c   = tid + i * THREADS;
        int r   = c >> 4;
        int off = (c & 15) * 16;
        CP_ASYNC16(dst + r * AS8 + off,
                   (const char*)g_q + (size_t)(grow0 + r) * 256 + off);
    }
}
__device__ __forceinline__ void load_half_async(uint32_t dst, int grow0) {
    const int wtid = threadIdx.x & 255;
    #pragma unroll
    for (int i = 0; i < 4; i++) {
        int c   = wtid + i * 256;      // 0..1023 : 64 rows x 16 chunks
        int r   = c >> 4;
        int off = (c & 15) * 16;
        CP_ASYNC16(dst + r * AS8 + off,
                   (const char*)g_q + (size_t)(grow0 + r) * 256 + off);
    }
}

// ---------------------------------------------------------------------------
// Main: upper-triangle tile sweep with symmetry, int8 mma m16n8k32.
// Each CTA tile (128x128) is split into two 64-col halves, each owned by an
// 8-warp warp-group with its OWN double-buffered B smem and its OWN named
// barrier -> the two warp-groups drift out of phase, overlapping epilogue
// (MUFU/ALU) of one group with mainloop (tensor/LDSM) of the other, breaking
// the full-CTA barrier convoy seen in R9 (all pipes ~30-50%, none saturated).
// ---------------------------------------------------------------------------
__global__ void __launch_bounds__(THREADS, 2) k_main(float* out) {
    extern __shared__ char sm[];
    __shared__ unsigned s_last;
    __shared__ float red[16];
    const uint32_t sA = smem_u32(sm);

    const int tid  = threadIdx.x;
    const int lane = tid & 31;
    const int warp = tid >> 5;
    const int wm   = warp & 3;             // M subtile (32 rows)
    const int wn2  = (warp >> 2) & 1;      // N subtile within half (32 cols)
    const int wg   = warp >> 3;            // warp-group 0/1 = column half
    const int l4   = lane >> 2;
    const int lm   = lane & 3;

    const uint32_t sBwg = sA + TILE8 + (uint32_t)wg * (2 * HB);

    const int p    = blockIdx.x / NCHUNK;  // strip pair 0..31
    const int h    = blockIdx.x % NCHUNK;  // chunk 0..8
    const int len1 = NRB - p;              // tiles in row-block p (J = p..63)
    const int t0   = (65 * h) / NCHUNK;
    const int t1   = (65 * (h + 1)) / NCHUNK;

    // ldmatrix per-lane base offsets (bytes); k-step adds ks*32
    uint32_t aoff[2];
    #pragma unroll
    for (int m = 0; m < 2; m++) {
        int arow = wm * 32 + m * 16 + (lane & 15);
        aoff[m] = sA + (uint32_t)arow * AS8 + (uint32_t)(lane >> 4) * 16;
    }
    uint32_t boff[2];
    #pragma unroll
    for (int nb = 0; nb < 2; nb++) {
        int brow = wn2 * 32 + nb * 16 + (lane & 7) + ((lane >> 4) << 3);
        boff[nb] = (uint32_t)brow * AS8 + (uint32_t)((lane >> 3) & 1) * 16;
    }

    #define I_OF(t) (((t) < len1) ? p : (NRB - 1 - p))
    #define J_OF(t) (((t) < len1) ? (p + (t)) : ((NRB - 1 - p) + ((t) - len1)))
    #define BUF(t)  (sBwg + (uint32_t)(((t) - t0) & 1) * HB)

    // ---- prologue: load A + first B half, publish to whole CTA ----
    int curI = I_OF(t0);
    load_tile_async(sA, curI * MT);
    load_half_async(BUF(t0), J_OF(t0) * CT + wg * 64);
    CP_COMMIT();
    CP_WAIT(0);
    __syncthreads();

    // exp(cos/T) = 2^(dot_i32 * KQ);  KQ = log2(e)/(T*127^2)
    const float KQ   = 2.8853900817779268f / 16129.0f;
    const float KP   = 2.0f / 16129.0f;
    const float MAGF = 12582912.0f;               // 1.5 * 2^23
    const int   MAGI = 0x4B400000;
    const float BQ   = -MAGF * KQ;
    const float BP   = -MAGF * KP;
    float rs[2][2] = {{0.f, 0.f}, {0.f, 0.f}};

    for (int t = t0; t < t1; t++) {
        const int J = J_OF(t);
        const uint32_t bufc = BUF(t);
        BARWG(wg);                        // wg done reading the buffer we overwrite
        const bool nextSame = (t + 1 < t1) && (I_OF(t + 1) == curI);
        if (nextSame) {
            load_half_async(BUF(t + 1), J_OF(t + 1) * CT + wg * 64);
            CP_COMMIT();
            CP_WAIT(1);
        } else {
            CP_WAIT(0);
        }
        BARWG(wg);                        // half-tile t visible to this wg

        int acc[2][4][4];
        #pragma unroll
        for (int m = 0; m < 2; m++)
            #pragma unroll
            for (int n = 0; n < 4; n++)
                #pragma unroll
                for (int c = 0; c < 4; c++) acc[m][n][c] = 0;

        #pragma unroll
        for (int ks = 0; ks < 8; ks++) {
            const uint32_t kb = (uint32_t)ks * 32;
            uint32_t a[2][4], b[2][4];
            LDSM_X4(a[0][0], a[0][1], a[0][2], a[0][3], aoff[0] + kb);
            LDSM_X4(a[1][0], a[1][1], a[1][2], a[1][3], aoff[1] + kb);
            LDSM_X4(b[0][0], b[0][1], b[0][2], b[0][3], bufc + boff[0] + kb);
            LDSM_X4(b[1][0], b[1][1], b[1][2], b[1][3], bufc + boff[1] + kb);
            #pragma unroll
            for (int m = 0; m < 2; m++)
                #pragma unroll
                for (int nb = 0; nb < 2; nb++) {
                    MMAS8(acc[m][nb*2+0], a[m][0], a[m][1], a[m][2], a[m][3],
                          b[nb][0], b[nb][1]);
                    MMAS8(acc[m][nb*2+1], a[m][0], a[m][1], a[m][2], a[m][3],
                          b[nb][2], b[nb][3]);
                }
        }

        // ---- epilogue ----
        const bool isDiag = (curI == J);
        const bool isPos  = (J == curI + BHALF / CT);
        const int rowb = curI * MT;
        const int gcb  = J * CT + wg * 64 + wn2 * 32;   // this warp's col base
        float cs[8];
        #pragma unroll
        for (int k = 0; k < 8; k++) cs[k] = 0.0f;

        #pragma unroll
        for (int m = 0; m < 2; m++) {
            #pragma unroll
            for (int n = 0; n < 4; n++) {
                #pragma unroll
                for (int c = 0; c < 4; c++) {
                    // exact i32->f32 via magic (|dot| <= 127^2*256 < 2^22)
                    float f = __int_as_float(MAGI + acc[m][n][c]);
                    float e = ex2f(fmaf(f, KQ, BQ));
                    if (isDiag) {
                        int gr = rowb + wm * 32 + m * 16 + ((c >> 1) << 3) + l4;
                        int gc = gcb + n * 8 + lm * 2 + (c & 1);
                        if (gc == gr) e = 0.0f;      // mask self-similarity
                    } else {
                        if (isPos) {
                            int gr = rowb + wm * 32 + m * 16 + ((c >> 1) << 3) + l4;
                            int gc = gcb + n * 8 + lm * 2 + (c & 1);
                            if (gc == gr + BHALF) {  // positive pair
                                float pv = fmaf(f, KP, BP);    // sim = cos/T
                                g_pos[gr] = pv;
                                g_pos[gc] = pv;      // symmetric partner
                            }
                        }
                        cs[n * 2 + (c & 1)] += e;    // column partial (symmetry)
                    }
                    rs[m][c >> 1] += e;              // row partial
                }
            }
        }

        if (!isDiag) {
            // reduce col partials over the 8 l4-lanes, then REDG to g_rowsum
            #pragma unroll
            for (int k = 0; k < 8; k++) {
                float v = cs[k];
                v += __shfl_xor_sync(0xffffffffu, v, 4);
                v += __shfl_xor_sync(0xffffffffu, v, 8);
                v += __shfl_xor_sync(0xffffffffu, v, 16);
                if (l4 == 0)
                    atomicAdd(&g_rowsum[gcb + (k >> 1) * 8 + lm * 2 + (k & 1)], v);
            }
        }

        // phase switch: flush row sums for curI, reload A (full-CTA barriers)
        if (t + 1 < t1 && !nextSame) {
            #pragma unroll
            for (int m = 0; m < 2; m++)
                #pragma unroll
                for (int h2 = 0; h2 < 2; h2++) {
                    float v = rs[m][h2];
                    v += __shfl_xor_sync(0xffffffffu, v, 1);
                    v += __shfl_xor_sync(0xffffffffu, v, 2);
                    if (lm == 0)
                        atomicAdd(&g_rowsum[curI * MT + wm * 32 + m * 16 + h2 * 8 + l4], v);
                    rs[m][h2] = 0.0f;
                }
            __syncthreads();              // whole CTA done with old A
            curI = I_OF(t + 1);
            load_tile_async(sA, curI * MT);
            load_half_async(BUF(t + 1), J_OF(t + 1) * CT + wg * 64);
            CP_COMMIT();
            CP_WAIT(0);
            __syncthreads();              // publish new A to whole CTA
        }
    }

    // final row-sum flush
    #pragma unroll
    for (int m = 0; m < 2; m++)
        #pragma unroll
        for (int h2 = 0; h2 < 2; h2++) {
            float v = rs[m][h2];
            v += __shfl_xor_sync(0xffffffffu, v, 1);
            v += __shfl_xor_sync(0xffffffffu, v, 2);
            if (lm == 0)
                atomicAdd(&g_rowsum[curI * MT + wm * 32 + m * 16 + h2 * 8 + l4], v);
        }

    // ---- completion ticket: last CTA does the final reduction ----
    __threadfence();                      // every thread: my atomics are visible
    __syncthreads();
    if (tid == 0) s_last = atomicInc(&g_ticket, NCTA - 1u);  // 288th sees 287 -> wraps 0
    __syncthreads();
    if (s_last == NCTA - 1u) {
        float acc = 0.0f;
        #pragma unroll
        for (int i = 0; i < 4; i++) {
            int r = (tid + i * THREADS) * 4;
            float4 s  = __ldcg((const float4*)(g_rowsum + r));
            float4 pp = __ldcg((const float4*)(g_pos + r));
            acc += (__logf(s.x) - pp.x) + (__logf(s.y) - pp.y)
                 + (__logf(s.z) - pp.z) + (__logf(s.w) - pp.w);
        }
        #pragma unroll
        for (int o = 16; o; o >>= 1) acc += __shfl_xor_sync(0xffffffffu, acc, o);
        if (lane == 0) red[warp] = acc;
        __syncthreads();
        if (tid == 0) {
            float v = 0.0f;
            #pragma unroll
            for (int w = 0; w < 16; w++) v += red[w];
            out[0] = v * (1.0f / NTOT);
        }
    }
    #undef I_OF
    #undef J_OF
    #undef BUF
}

// ---------------------------------------------------------------------------
extern "C" void kernel_launch(void* const* d_in, const int* in_sizes, int n_in,
                              void* d_out, int out_size) {
    const float* zi = (const float*)d_in[0];
    const float* zj = (const float*)d_in[1];
    float* out = (float*)d_out;

    const size_t smem = (size_t)TILE8 + 4 * HB;   // A + 2wg x 2buf = 104,448 B
    cudaFuncSetAttribute(k_main, cudaFuncAttributeMaxDynamicSharedMemorySize, (int)smem);

    k_prep<<<NTOT / 32, 256>>>(zi, zj);
    k_main<<<NCTA, THREADS, smem>>>(out);
}

// round 11
// speedup vs baseline: 1.0826x; 1.0826x over previous
#include <cuda_runtime.h>
#include <cuda_bf16.h>
#include <math.h>
#include <stdint.h>

#define NTOT   8192
#define BHALF  4096
#define DDIM   256
#define MT     128                  // rows per tile-block
#define CT     128                  // cols per tile
#define NRB    (NTOT / MT)          // 64 row-blocks
#define AS8    272                  // smem row stride bytes (256 data + 16 pad)
#define TILE8  (MT * AS8)           // 34816 bytes per tile buffer
#define NCHUNK 9                    // chunks per strip-pair -> grid 288 = 2 CTAs/SM
#define NCTA   (32 * NCHUNK)        // 288
#define THREADS 512

// Scratch: int8-quantized normalized vectors (q = round(127*zhat)),
// per-row sum-exp, per-row positive logit, completion ticket
__device__ int8_t g_q[NTOT * DDIM];
__device__ float g_rowsum[NTOT];
__device__ float g_pos[NTOT];
__device__ unsigned g_ticket;

// ---------------------------------------------------------------------------
__device__ __forceinline__ uint32_t smem_u32(const void* p) {
    uint32_t a;
    asm("{ .reg .u64 t; cvta.to.shared.u64 t, %1; cvt.u32.u64 %0, t; }"
        : "=r"(a) : "l"(p));
    return a;
}
__device__ __forceinline__ float ex2f(float x) {     // 2^x on MUFU pipe
    float r;
    asm("ex2.approx.f32 %0, %1;" : "=f"(r) : "f"(x));
    return r;
}
#define CP_ASYNC16(dst, src) \
    asm volatile("cp.async.cg.shared.global [%0], [%1], 16;" :: "r"(dst), "l"(src))
#define CP_COMMIT() asm volatile("cp.async.commit_group;" ::: "memory")
#define CP_WAIT(n)  asm volatile("cp.async.wait_group %0;" :: "n"(n) : "memory")

#define LDSM_X4(r0, r1, r2, r3, a)                                        \
    asm volatile("ldmatrix.sync.aligned.m8n8.x4.shared.b16 {%0,%1,%2,%3}, [%4];" \
        : "=r"(r0), "=r"(r1), "=r"(r2), "=r"(r3) : "r"(a))

#define MMAS8(d, a0, a1, a2, a3, b0, b1)                                  \
    asm volatile("mma.sync.aligned.m16n8k32.row.col.s32.s8.s8.s32 "       \
        "{%0,%1,%2,%3}, {%4,%5,%6,%7}, {%8,%9}, {%0,%1,%2,%3};"           \
        : "+r"((d)[0]), "+r"((d)[1]), "+r"((d)[2]), "+r"((d)[3])          \
        : "r"(a0), "r"(a1), "r"(a2), "r"(a3), "r"(b0), "r"(b1))

// ---------------------------------------------------------------------------
// Prep: each warp handles 4 rows, 8 LDG.128 in flight, 4 parallel reductions.
// Also zeroes g_rowsum / g_ticket.
// ---------------------------------------------------------------------------
__device__ __forceinline__ const float* row_ptr(int row,
        const float* zi, const float* zj) {
    return (row < BHALF) ? (zi + (size_t)row * DDIM)
                         : (zj + (size_t)(row - BHALF) * DDIM);
}
__device__ __forceinline__ void quant_store(int row, float sc,
        float4 v0, float4 v1, int lane) {
    int q0 = __float2int_rn(v0.x * sc), q1 = __float2int_rn(v0.y * sc);
    int q2 = __float2int_rn(v0.z * sc), q3 = __float2int_rn(v0.w * sc);
    int q4 = __float2int_rn(v1.x * sc), q5 = __float2int_rn(v1.y * sc);
    int q6 = __float2int_rn(v1.z * sc), q7 = __float2int_rn(v1.w * sc);
    uint2 pk;
    pk.x = (q0 & 0xff) | ((q1 & 0xff) << 8) | ((q2 & 0xff) << 16) | (q3 << 24);
    pk.y = (q4 & 0xff) | ((q5 & 0xff) << 8) | ((q6 & 0xff) << 16) | (q7 << 24);
    *(uint2*)(g_q + (size_t)row * DDIM + lane * 8) = pk;
}

__global__ void k_prep(const float* __restrict__ zi, const float* __restrict__ zj) {
    if (blockIdx.x < 32) g_rowsum[blockIdx.x * 256 + threadIdx.x] = 0.0f;
    if (blockIdx.x == 0 && threadIdx.x == 0) g_ticket = 0u;

    const int warp = threadIdx.x >> 5;
    const int lane = threadIdx.x & 31;
    const int r0 = blockIdx.x * 32 + warp * 4;

    float4 v[8];
    #pragma unroll
    for (int r = 0; r < 4; r++) {
        const float* s = row_ptr(r0 + r, zi, zj);
        v[2*r]   = ((const float4*)s)[lane * 2 + 0];
        v[2*r+1] = ((const float4*)s)[lane * 2 + 1];
    }
    float ss[4];
    #pragma unroll
    for (int r = 0; r < 4; r++) {
        float4 a = v[2*r], b = v[2*r+1];
        ss[r] = a.x*a.x + a.y*a.y + a.z*a.z + a.w*a.w
              + b.x*b.x + b.y*b.y + b.z*b.z + b.w*b.w;
    }
    #pragma unroll
    for (int o = 16; o; o >>= 1)
        #pragma unroll
        for (int r = 0; r < 4; r++)
            ss[r] += __shfl_xor_sync(0xffffffffu, ss[r], o);
    #pragma unroll
    for (int r = 0; r < 4; r++)
        quant_store(r0 + r, 127.0f * rsqrtf(ss[r]), v[2*r], v[2*r+1], lane);
}

// ---------------------------------------------------------------------------
// Async tile loader: 128 rows x 256 int8; 2048 16B chunks over 512 threads.
// ---------------------------------------------------------------------------
__device__ __forceinline__ void load_tile_async(uint32_t dst, int grow0) {
    const int tid = threadIdx.x;
    #pragma unroll
    for (int i = 0; i < 4; i++) {
        int c   = tid + i * THREADS;
        int r   = c >> 4;
        int off = (c & 15) * 16;
        CP_ASYNC16(dst + r * AS8 + off,
                   (const char*)g_q + (size_t)(grow0 + r) * 256 + off);
    }
}

// ---------------------------------------------------------------------------
// Main: upper-triangle tile sweep with symmetry, int8 mma m16n8k32.
// R11: epilogue instruction diet — accumulators pre-biased with the i32->f32
// magic constant (MMA adds dot on top, so no per-element IADD), and the
// per-element diag/pos predicate logic is hoisted to a tile-level fast/slow
// path split (only ~2 of 65 tiles per strip take the slow path).
// ---------------------------------------------------------------------------
__global__ void __launch_bounds__(THREADS, 2) k_main(float* out) {
    extern __shared__ char sm[];
    __shared__ unsigned s_last;
    __shared__ float red[16];
    const uint32_t sA  = smem_u32(sm);
    const uint32_t sB0 = sA + TILE8;

    const int tid  = threadIdx.x;
    const int lane = tid & 31;
    const int warp = tid >> 5;
    const int wm   = warp & 3;             // M subtile (32 rows)
    const int wn   = warp >> 2;            // N subtile (32 cols), 0..3
    const int l4   = lane >> 2;
    const int lm   = lane & 3;

    const int p    = blockIdx.x / NCHUNK;  // strip pair 0..31
    const int h    = blockIdx.x % NCHUNK;  // chunk 0..8
    const int len1 = NRB - p;              // tiles in row-block p (J = p..63)
    const int t0   = (65 * h) / NCHUNK;
    const int t1   = (65 * (h + 1)) / NCHUNK;

    // ldmatrix per-lane base offsets (bytes); k-step adds ks*32
    uint32_t aoff[2];
    #pragma unroll
    for (int m = 0; m < 2; m++) {
        int arow = wm * 32 + m * 16 + (lane & 15);
        aoff[m] = sA + (uint32_t)arow * AS8 + (uint32_t)(lane >> 4) * 16;
    }
    uint32_t boff[2];
    #pragma unroll
    for (int nb = 0; nb < 2; nb++) {
        int brow = wn * 32 + nb * 16 + (lane & 7) + ((lane >> 4) << 3);
        boff[nb] = (uint32_t)brow * AS8 + (uint32_t)((lane >> 3) & 1) * 16;
    }

    #define I_OF(t) (((t) < len1) ? p : (NRB - 1 - p))
    #define J_OF(t) (((t) < len1) ? (p + (t)) : ((NRB - 1 - p) + ((t) - len1)))
    #define BUF(t)  (sB0 + (uint32_t)(((t) - t0) & 1) * TILE8)

    int curI = I_OF(t0);
    load_tile_async(sA, curI * MT);
    load_tile_async(BUF(t0), J_OF(t0) * CT);
    CP_COMMIT();

    // exp(cos/T) = 2^(dot_i32 * KQ);  KQ = log2(e)/(T*127^2)
    const float KQ   = 2.8853900817779268f / 16129.0f;
    const float KP   = 2.0f / 16129.0f;
    const float MAGF = 12582912.0f;               // 1.5 * 2^23
    const int   MAGI = 0x4B400000;
    const float BQ   = -MAGF * KQ;
    const float BP   = -MAGF * KP;
    float rs[2][2] = {{0.f, 0.f}, {0.f, 0.f}};

    for (int t = t0; t < t1; t++) {
        const int J = J_OF(t);
        const uint32_t bufc = BUF(t);
        __syncthreads();                  // all done reading the buffer we overwrite
        const bool nextSame = (t + 1 < t1) && (I_OF(t + 1) == curI);
        if (nextSame) {
            load_tile_async(BUF(t + 1), J_OF(t + 1) * CT);
            CP_COMMIT();
            CP_WAIT(1);
        } else {
            CP_WAIT(0);
        }
        __syncthreads();                  // tile t visible to all threads

        // Pre-biased accumulators: MMA chain yields MAGI + dot, whose bit
        // pattern IS the float (MAGF + dot) -> no per-element IADD later.
        int acc[2][4][4];
        #pragma unroll
        for (int m = 0; m < 2; m++)
            #pragma unroll
            for (int n = 0; n < 4; n++) {
                acc[m][n][0] = MAGI; acc[m][n][1] = MAGI;
                acc[m][n][2] = MAGI; acc[m][n][3] = MAGI;
            }

        #pragma unroll
        for (int ks = 0; ks < 8; ks++) {
            const uint32_t kb = (uint32_t)ks * 32;
            uint32_t a[2][4], b[2][4];
            LDSM_X4(a[0][0], a[0][1], a[0][2], a[0][3], aoff[0] + kb);
            LDSM_X4(a[1][0], a[1][1], a[1][2], a[1][3], aoff[1] + kb);
            LDSM_X4(b[0][0], b[0][1], b[0][2], b[0][3], bufc + boff[0] + kb);
            LDSM_X4(b[1][0], b[1][1], b[1][2], b[1][3], bufc + boff[1] + kb);
            #pragma unroll
            for (int m = 0; m < 2; m++)
                #pragma unroll
                for (int nb = 0; nb < 2; nb++) {
                    MMAS8(acc[m][nb*2+0], a[m][0], a[m][1], a[m][2], a[m][3],
                          b[nb][0], b[nb][1]);
                    MMAS8(acc[m][nb*2+1], a[m][0], a[m][1], a[m][2], a[m][3],
                          b[nb][2], b[nb][3]);
                }
        }

        // ---- epilogue ----
        const bool isDiag = (curI == J);
        const bool isPos  = (J == curI + BHALF / CT);
        const int colb = J * CT;
        float cs[8];
        #pragma unroll
        for (int k = 0; k < 8; k++) cs[k] = 0.0f;

        if (!isDiag && !isPos) {
            // FAST PATH (~63/65 tiles): no indices, no predicates.
            #pragma unroll
            for (int m = 0; m < 2; m++)
                #pragma unroll
                for (int n = 0; n < 4; n++)
                    #pragma unroll
                    for (int c = 0; c < 4; c++) {
                        float e = ex2f(fmaf(__int_as_float(acc[m][n][c]), KQ, BQ));
                        rs[m][c >> 1]        += e;   // row partial
                        cs[n * 2 + (c & 1)]  += e;   // column partial (symmetry)
                    }
        } else {
            // SLOW PATH: diagonal tile (mask self-sim, no col contribution)
            // or positive tile (capture pos logits, col contribution kept).
            const int rowb = curI * MT;
            #pragma unroll
            for (int m = 0; m < 2; m++) {
                #pragma unroll
                for (int n = 0; n < 4; n++) {
                    #pragma unroll
                    for (int c = 0; c < 4; c++) {
                        float f = __int_as_float(acc[m][n][c]);
                        float e = ex2f(fmaf(f, KQ, BQ));
                        int gr = rowb + wm * 32 + m * 16 + ((c >> 1) << 3) + l4;
                        int gc = colb + wn * 32 + n * 8 + lm * 2 + (c & 1);
                        if (isDiag) {
                            if (gc == gr) e = 0.0f;          // mask self-similarity
                        } else {
                            if (gc == gr + BHALF) {          // positive pair
                                float pv = fmaf(f, KP, BP);  // sim = cos/T
                                g_pos[gr] = pv;
                                g_pos[gc] = pv;              // symmetric partner
                            }
                            cs[n * 2 + (c & 1)] += e;
                        }
                        rs[m][c >> 1] += e;
                    }
                }
            }
        }

        if (!isDiag) {
            // reduce col partials over the 8 l4-lanes, then REDG to g_rowsum
            #pragma unroll
            for (int k = 0; k < 8; k++) {
                float v = cs[k];
                v += __shfl_xor_sync(0xffffffffu, v, 4);
                v += __shfl_xor_sync(0xffffffffu, v, 8);
                v += __shfl_xor_sync(0xffffffffu, v, 16);
                if (l4 == 0)
                    atomicAdd(&g_rowsum[colb + wn * 32 + (k >> 1) * 8 + lm * 2 + (k & 1)], v);
            }
        }

        // phase switch: flush row sums for curI, reload A in place
        if (t + 1 < t1 && !nextSame) {
            #pragma unroll
            for (int m = 0; m < 2; m++)
                #pragma unroll
                for (int h2 = 0; h2 < 2; h2++) {
                    float v = rs[m][h2];
                    v += __shfl_xor_sync(0xffffffffu, v, 1);
                    v += __shfl_xor_sync(0xffffffffu, v, 2);
                    if (lm == 0)
                        atomicAdd(&g_rowsum[curI * MT + wm * 32 + m * 16 + h2 * 8 + l4], v);
                    rs[m][h2] = 0.0f;
                }
            __syncthreads();              // all warps done with old A
            curI = I_OF(t + 1);
            load_tile_async(sA, curI * MT);
            load_tile_async(BUF(t + 1), J_OF(t + 1) * CT);
            CP_COMMIT();
        }
    }

    // final row-sum flush
    #pragma unroll
    for (int m = 0; m < 2; m++)
        #pragma unroll
        for (int h2 = 0; h2 < 2; h2++) {
            float v = rs[m][h2];
            v += __shfl_xor_sync(0xffffffffu, v, 1);
            v += __shfl_xor_sync(0xffffffffu, v, 2);
            if (lm == 0)
                atomicAdd(&g_rowsum[curI * MT + wm * 32 + m * 16 + h2 * 8 + l4], v);
        }

    // ---- completion ticket: last CTA does the final reduction ----
    __threadfence();
    __syncthreads();
    if (tid == 0) s_last = atomicInc(&g_ticket, NCTA - 1u);  // 288th sees 287 -> wraps 0
    __syncthreads();
    if (s_last == NCTA - 1u) {
        float acc = 0.0f;
        #pragma unroll
        for (int i = 0; i < 4; i++) {
            int r = (tid + i * THREADS) * 4;
            float4 s  = __ldcg((const float4*)(g_rowsum + r));
            float4 pp = __ldcg((const float4*)(g_pos + r));
            acc += (__logf(s.x) - pp.x) + (__logf(s.y) - pp.y)
                 + (__logf(s.z) - pp.z) + (__logf(s.w) - pp.w);
        }
        #pragma unroll
        for (int o = 16; o; o >>= 1) acc += __shfl_xor_sync(0xffffffffu, acc, o);
        if (lane == 0) red[warp] = acc;
        __syncthreads();
        if (tid == 0) {
            float v = 0.0f;
            #pragma unroll
            for (int w = 0; w < 16; w++) v += red[w];
            out[0] = v * (1.0f / NTOT);
        }
    }
    #undef I_OF
    #undef J_OF
    #undef BUF
}

// ---------------------------------------------------------------------------
extern "C" void kernel_launch(void* const* d_in, const int* in_sizes, int n_in,
                              void* d_out, int out_size) {
    const float* zi = (const float*)d_in[0];
    const float* zj = (const float*)d_in[1];
    float* out = (float*)d_out;

    const size_t smem = (size_t)TILE8 * 3;   // A + 2x B = 104,448 B (2 CTAs/SM)
    cudaFuncSetAttribute(k_main, cudaFuncAttributeMaxDynamicSharedMemorySize, (int)smem);

    k_prep<<<NTOT / 32, 256>>>(zi, zj);
    k_main<<<NCTA, THREADS, smem>>>(out);
}